// round 3
// baseline (speedup 1.0000x reference)
#include <cuda_runtime.h>
#include <math.h>

#define BB 4
#define NN 3000
#define CC 21
#define BN (BB*NN)

// scratch (no allocations allowed)
__device__ signed char g_amax[BN];
__device__ float       g_score[BN];

// ---------------------------------------------------------------------------
// Kernel A: elementwise prep.
// out layout (float32, concatenated ref outputs):
//   [0, BN*4)            nms_reg_rounded
//   [BN*4, BN*5)         sigmoid(nms_cls)
//   [BN*5, BN*9)         boxes
//   [BN*9, BN*9+BN*C)    probs
//   [BN*9+BN*C, ...)     keep (0/1 as float)
// ---------------------------------------------------------------------------
__global__ void prep_kernel(const float* __restrict__ nms_reg,
                            const float* __restrict__ nms_cls,
                            const float* __restrict__ rcnn_reg,
                            const float* __restrict__ rcnn_cls,
                            const unsigned int* __restrict__ red_raw,
                            float* __restrict__ out)
{
    int idx = blockIdx.x * blockDim.x + threadIdx.x;
    if (idx >= BN) return;

    // reduction may be stored as int32 or float32; disambiguate by bit pattern.
    unsigned int w = red_raw[0];
    float red = (w < 0x10000u) ? (float)w : __uint_as_float(w);

    float* o_round = out;
    float* o_sig   = out + BN * 4;
    float* o_boxes = out + BN * 5;
    float* o_probs = out + BN * 9;
    float* o_keep  = out + BN * 9 + BN * CC;

    // rounded boxes + boxes
    float r0 = nms_reg[idx * 4 + 0];
    float r1 = nms_reg[idx * 4 + 1];
    float r2 = nms_reg[idx * 4 + 2];
    float r3 = nms_reg[idx * 4 + 3];
    float q0 = floorf(__fmul_rn(r0, red)) / red;
    float q1 = floorf(__fmul_rn(r1, red)) / red;
    float q2 = ceilf(__fmul_rn(r2, red)) / red;
    float q3 = ceilf(__fmul_rn(r3, red)) / red;
    o_round[idx * 4 + 0] = q0;
    o_round[idx * 4 + 1] = q1;
    o_round[idx * 4 + 2] = q2;
    o_round[idx * 4 + 3] = q3;

    o_boxes[idx * 4 + 0] = __fadd_rn(rcnn_reg[idx * 4 + 0], q0);
    o_boxes[idx * 4 + 1] = __fadd_rn(rcnn_reg[idx * 4 + 1], q1);
    o_boxes[idx * 4 + 2] = __fadd_rn(rcnn_reg[idx * 4 + 2], q2);
    o_boxes[idx * 4 + 3] = __fadd_rn(rcnn_reg[idx * 4 + 3], q3);

    // sigmoid
    float s = nms_cls[idx];
    o_sig[idx] = 1.0f / (1.0f + expf(-s));

    // softmax + argmax
    float logit[CC];
    float m = -INFINITY;
    #pragma unroll
    for (int c = 0; c < CC; c++) {
        logit[c] = rcnn_cls[idx * CC + c];
        m = fmaxf(m, logit[c]);
    }
    float sum = 0.0f;
    float p[CC];
    #pragma unroll
    for (int c = 0; c < CC; c++) {
        p[c] = expf(logit[c] - m);
        sum += p[c];
    }
    float inv = 1.0f / sum;
    int   am   = 0;
    float best = -INFINITY;
    #pragma unroll
    for (int c = 0; c < CC; c++) {
        p[c] = __fmul_rn(p[c], inv);
        o_probs[idx * CC + c] = p[c];
        if (p[c] > best) { best = p[c]; am = c; }
    }
    g_amax[idx]  = (signed char)am;
    g_score[idx] = best;

    // zero keep (d_out is poisoned)
    o_keep[idx] = 0.0f;
}

// ---------------------------------------------------------------------------
// Kernel B: per-(batch,class) greedy NMS. One block per group.
//
// NOTE (reference quirk): the reference's lax.scan runs all N iterations; once
// candidates are exhausted, argmax over an all -inf array returns index 0 and
// keep[0] is overwritten with False. Hence in-batch box index 0 is NEVER kept.
// We replicate this by skipping the keep write for ni == 0 (the box still
// participates in suppression, matching the scan's rem updates).
// ---------------------------------------------------------------------------
#define SORT_N 4096
#define NMS_THREADS 256

__global__ void __launch_bounds__(NMS_THREADS)
nms_kernel(float* __restrict__ out)
{
    __shared__ unsigned long long keys[SORT_N];
    __shared__ unsigned char sup[SORT_N];
    __shared__ int s_count;

    const float* boxes = out + BN * 5;
    float*       keep  = out + BN * 9 + BN * CC;

    int b   = blockIdx.x / (CC - 1);
    int cls = 1 + blockIdx.x % (CC - 1);
    int tid = threadIdx.x;

    if (tid == 0) s_count = 0;
    __syncthreads();

    // gather candidates of this class
    for (int n = tid; n < NN; n += NMS_THREADS) {
        if ((int)g_amax[b * NN + n] == cls) {
            int pos = atomicAdd(&s_count, 1);
            unsigned int sb = __float_as_uint(g_score[b * NN + n]); // positive -> monotone bits
            keys[pos] = ((unsigned long long)sb << 32)
                      | (unsigned long long)(0xFFFFFFFFu - (unsigned)n);
        }
    }
    __syncthreads();
    int M = s_count;
    if (M == 0) return;

    // pad to next power of two >= M
    int P = 1;
    while (P < M) P <<= 1;
    for (int i = M + tid; i < P; i += NMS_THREADS) keys[i] = 0ULL;
    __syncthreads();

    // bitonic sort over P elements, descending (score desc, index asc on ties)
    for (int k = 2; k <= P; k <<= 1) {
        for (int j = k >> 1; j > 0; j >>= 1) {
            for (int i = tid; i < P; i += NMS_THREADS) {
                int ixj = i ^ j;
                if (ixj > i) {
                    unsigned long long a = keys[i];
                    unsigned long long c = keys[ixj];
                    bool dirDesc = ((i & k) == 0);
                    if ((a < c) == dirDesc) { keys[i] = c; keys[ixj] = a; }
                }
            }
            __syncthreads();
        }
    }

    for (int i = tid; i < M; i += NMS_THREADS) sup[i] = 0;
    __syncthreads();

    // exact sequential greedy NMS with block-parallel suppression.
    // IOU uses explicit non-fused fp32 ops so results are bit-identical to the
    // reference's separate mul/add/sub (no FMA contraction).
    for (int i = 0; i < M; i++) {
        if (!sup[i]) {   // uniform: sup[] is shared
            unsigned long long ki = keys[i];
            int ni = (int)(0xFFFFFFFFu - (unsigned)(ki & 0xFFFFFFFFu));
            const float* bi_p = boxes + (size_t)(b * NN + ni) * 4;
            float ti = bi_p[0], li = bi_p[1], bi = bi_p[2], ri = bi_p[3];
            float ai = __fmul_rn(fmaxf(__fsub_rn(bi, ti), 0.0f),
                                 fmaxf(__fsub_rn(ri, li), 0.0f));
            if (tid == 0 && ni != 0) keep[b * NN + ni] = 1.0f;
            for (int j = i + 1 + tid; j < M; j += NMS_THREADS) {
                if (sup[j]) continue;
                unsigned long long kj = keys[j];
                int nj = (int)(0xFFFFFFFFu - (unsigned)(kj & 0xFFFFFFFFu));
                const float* bj_p = boxes + (size_t)(b * NN + nj) * 4;
                float tj = bj_p[0], lj = bj_p[1], bj = bj_p[2], rj = bj_p[3];
                float aj = __fmul_rn(fmaxf(__fsub_rn(bj, tj), 0.0f),
                                     fmaxf(__fsub_rn(rj, lj), 0.0f));
                float ih = fmaxf(__fsub_rn(fminf(bi, bj), fmaxf(ti, tj)), 0.0f);
                float iw = fmaxf(__fsub_rn(fminf(ri, rj), fmaxf(li, lj)), 0.0f);
                float inter = __fmul_rn(ih, iw);
                float uni   = __fsub_rn(__fadd_rn(ai, aj), inter);
                float iou   = __fdiv_rn(inter, fmaxf(uni, 1e-9f));
                if (iou > 0.5f) sup[j] = 1;
            }
        }
        __syncthreads();
    }
}

extern "C" void kernel_launch(void* const* d_in, const int* in_sizes, int n_in,
                              void* d_out, int out_size)
{
    const float* nms_reg  = (const float*)d_in[0];
    const float* nms_cls  = (const float*)d_in[1];
    const float* rcnn_reg = (const float*)d_in[2];
    const float* rcnn_cls = (const float*)d_in[3];
    const unsigned int* red = (const unsigned int*)d_in[4];
    float* out = (float*)d_out;

    prep_kernel<<<(BN + 255) / 256, 256>>>(nms_reg, nms_cls, rcnn_reg, rcnn_cls, red, out);
    nms_kernel<<<BB * (CC - 1), NMS_THREADS>>>(out);
}

// round 4
// speedup vs baseline: 1.3400x; 1.3400x over previous
#include <cuda_runtime.h>
#include <math.h>

#define BB 4
#define NN 3000
#define CC 21
#define BN (BB*NN)

// scratch (no allocations allowed)
__device__ signed char g_amax[BN];
__device__ float       g_score[BN];

// ---------------------------------------------------------------------------
// Kernel A: elementwise prep.
// out layout (float32, concatenated ref outputs):
//   [0, BN*4)            nms_reg_rounded
//   [BN*4, BN*5)         sigmoid(nms_cls)
//   [BN*5, BN*9)         boxes
//   [BN*9, BN*9+BN*C)    probs
//   [BN*9+BN*C, ...)     keep (0/1 as float)
// ---------------------------------------------------------------------------
__global__ void prep_kernel(const float* __restrict__ nms_reg,
                            const float* __restrict__ nms_cls,
                            const float* __restrict__ rcnn_reg,
                            const float* __restrict__ rcnn_cls,
                            const unsigned int* __restrict__ red_raw,
                            float* __restrict__ out)
{
    int idx = blockIdx.x * blockDim.x + threadIdx.x;
    if (idx >= BN) return;

    unsigned int w = red_raw[0];
    float red = (w < 0x10000u) ? (float)w : __uint_as_float(w);

    float* o_round = out;
    float* o_sig   = out + BN * 4;
    float* o_boxes = out + BN * 5;
    float* o_probs = out + BN * 9;
    float* o_keep  = out + BN * 9 + BN * CC;

    float r0 = nms_reg[idx * 4 + 0];
    float r1 = nms_reg[idx * 4 + 1];
    float r2 = nms_reg[idx * 4 + 2];
    float r3 = nms_reg[idx * 4 + 3];
    float q0 = floorf(__fmul_rn(r0, red)) / red;
    float q1 = floorf(__fmul_rn(r1, red)) / red;
    float q2 = ceilf(__fmul_rn(r2, red)) / red;
    float q3 = ceilf(__fmul_rn(r3, red)) / red;
    o_round[idx * 4 + 0] = q0;
    o_round[idx * 4 + 1] = q1;
    o_round[idx * 4 + 2] = q2;
    o_round[idx * 4 + 3] = q3;

    o_boxes[idx * 4 + 0] = __fadd_rn(rcnn_reg[idx * 4 + 0], q0);
    o_boxes[idx * 4 + 1] = __fadd_rn(rcnn_reg[idx * 4 + 1], q1);
    o_boxes[idx * 4 + 2] = __fadd_rn(rcnn_reg[idx * 4 + 2], q2);
    o_boxes[idx * 4 + 3] = __fadd_rn(rcnn_reg[idx * 4 + 3], q3);

    float s = nms_cls[idx];
    o_sig[idx] = 1.0f / (1.0f + expf(-s));

    float logit[CC];
    float m = -INFINITY;
    #pragma unroll
    for (int c = 0; c < CC; c++) {
        logit[c] = rcnn_cls[idx * CC + c];
        m = fmaxf(m, logit[c]);
    }
    float sum = 0.0f;
    float p[CC];
    #pragma unroll
    for (int c = 0; c < CC; c++) {
        p[c] = expf(logit[c] - m);
        sum += p[c];
    }
    float inv = 1.0f / sum;
    int   am   = 0;
    float best = -INFINITY;
    #pragma unroll
    for (int c = 0; c < CC; c++) {
        p[c] = __fmul_rn(p[c], inv);
        o_probs[idx * CC + c] = p[c];
        if (p[c] > best) { best = p[c]; am = c; }
    }
    g_amax[idx]  = (signed char)am;
    g_score[idx] = best;

    o_keep[idx] = 0.0f;
}

// ---------------------------------------------------------------------------
// Kernel B: per-(batch,class) greedy NMS. One block per group.
//
// Fast path (M <= MAXM): precompute M x M suppression bit-matrix in parallel,
// then warp-level greedy bitmask scan (exactly equivalent to sequential greedy
// since suppression accumulates monotonically via OR).
//
// Reference quirk: in-batch box index 0 is never kept (scan's exhausted
// iterations argmax to 0 and overwrite keep[0] with False). Box 0 still
// suppresses others.
// ---------------------------------------------------------------------------
#define NMS_THREADS 256
#define MAXM  320
#define WMAX  10            // ceil(MAXM/32)
#define FB_SORT 4096        // fallback sort capacity

// sbuf overlay:
//   fast path:  keys  [0, 4096)            (u64 x up to 512, P<=512)
//               tlbr  [4096, 9216)         (float4 x MAXM)
//               area  [9216, 10496)        (float x MAXM)
//   fallback:   keys  [0, 32768)           (u64 x 4096)
__shared__ unsigned char sbuf[32768];
__shared__ unsigned int  maskbuf[MAXM * WMAX];   // fast path: bit matrix
                                                 // fallback: sup[] bytes
__shared__ int s_count;

__global__ void __launch_bounds__(NMS_THREADS)
nms_kernel(float* __restrict__ out)
{
    const float* boxes = out + BN * 5;
    float*       keep  = out + BN * 9 + BN * CC;

    int b   = blockIdx.x / (CC - 1);
    int cls = 1 + blockIdx.x % (CC - 1);
    int tid = threadIdx.x;

    unsigned long long* keys = (unsigned long long*)sbuf;

    if (tid == 0) s_count = 0;
    __syncthreads();

    // gather candidates of this class
    for (int n = tid; n < NN; n += NMS_THREADS) {
        if ((int)g_amax[b * NN + n] == cls) {
            int pos = atomicAdd(&s_count, 1);
            unsigned int sb = __float_as_uint(g_score[b * NN + n]);
            keys[pos] = ((unsigned long long)sb << 32)
                      | (unsigned long long)(0xFFFFFFFFu - (unsigned)n);
        }
    }
    __syncthreads();
    int M = s_count;
    if (M == 0) return;

    // pad to next power of two >= M
    int P = 1;
    while (P < M) P <<= 1;
    for (int i = M + tid; i < P; i += NMS_THREADS) keys[i] = 0ULL;
    __syncthreads();

    // bitonic sort, descending (score desc, index asc on ties)
    for (int k = 2; k <= P; k <<= 1) {
        for (int j = k >> 1; j > 0; j >>= 1) {
            for (int i = tid; i < P; i += NMS_THREADS) {
                int ixj = i ^ j;
                if (ixj > i) {
                    unsigned long long a = keys[i];
                    unsigned long long c = keys[ixj];
                    bool dirDesc = ((i & k) == 0);
                    if ((a < c) == dirDesc) { keys[i] = c; keys[ixj] = a; }
                }
            }
            __syncthreads();
        }
    }

    if (M <= MAXM) {
        // ---------------- fast path ----------------
        float4* tlbr = (float4*)(sbuf + 4096);
        float*  area = (float*)(sbuf + 9216);
        const int W = (M + 31) >> 5;

        // stage sorted boxes + areas into shared; zero bit matrix
        for (int i = tid; i < M; i += NMS_THREADS) {
            unsigned int n = 0xFFFFFFFFu - (unsigned)(keys[i] & 0xFFFFFFFFu);
            const float* bp = boxes + (size_t)(b * NN + (int)n) * 4;
            float4 v = make_float4(bp[0], bp[1], bp[2], bp[3]);
            tlbr[i] = v;
            area[i] = __fmul_rn(fmaxf(__fsub_rn(v.z, v.x), 0.0f),
                                fmaxf(__fsub_rn(v.w, v.y), 0.0f));
        }
        for (int t = tid; t < M * W; t += NMS_THREADS) maskbuf[t] = 0;
        __syncthreads();

        // build suppression matrix: bit j set in row i if iou(i,j) > 0.5, j > i
        int total = M * M;
        for (int t = tid; t < total; t += NMS_THREADS) {
            int i = t / M;
            int j = t - i * M;
            if (j <= i) continue;
            float4 bi = tlbr[i];
            float4 bj = tlbr[j];
            float ih = fmaxf(__fsub_rn(fminf(bi.z, bj.z), fmaxf(bi.x, bj.x)), 0.0f);
            float iw = fmaxf(__fsub_rn(fminf(bi.w, bj.w), fmaxf(bi.y, bj.y)), 0.0f);
            float inter = __fmul_rn(ih, iw);
            float uni   = __fsub_rn(__fadd_rn(area[i], area[j]), inter);
            float iou   = __fdiv_rn(inter, fmaxf(uni, 1e-9f));
            if (iou > 0.5f)
                atomicOr(&maskbuf[i * W + (j >> 5)], 1u << (j & 31));
        }
        __syncthreads();

        // warp 0: greedy bitmask scan. lane w owns removed-word w.
        if (tid < 32) {
            int lane = tid;
            unsigned int R = 0u;
            for (int i = 0; i < M; i++) {
                unsigned int rw = __shfl_sync(0xFFFFFFFFu, R, i >> 5);
                bool kept = !((rw >> (i & 31)) & 1u);
                if (kept) {
                    if (lane == 0) {
                        unsigned int n = 0xFFFFFFFFu - (unsigned)(keys[i] & 0xFFFFFFFFu);
                        if (n != 0u) keep[b * NN + (int)n] = 1.0f;
                    }
                    if (lane < W) R |= maskbuf[i * W + lane];
                }
            }
        }
    } else {
        // ---------------- fallback (never expected for this dataset) --------
        unsigned char* sup = (unsigned char*)maskbuf;
        for (int i = tid; i < M; i += NMS_THREADS) sup[i] = 0;
        __syncthreads();

        for (int i = 0; i < M; i++) {
            if (!sup[i]) {
                unsigned long long ki = keys[i];
                int ni = (int)(0xFFFFFFFFu - (unsigned)(ki & 0xFFFFFFFFu));
                const float* bi_p = boxes + (size_t)(b * NN + ni) * 4;
                float ti = bi_p[0], li = bi_p[1], bi = bi_p[2], ri = bi_p[3];
                float ai = __fmul_rn(fmaxf(__fsub_rn(bi, ti), 0.0f),
                                     fmaxf(__fsub_rn(ri, li), 0.0f));
                if (tid == 0 && ni != 0) keep[b * NN + ni] = 1.0f;
                for (int j = i + 1 + tid; j < M; j += NMS_THREADS) {
                    if (sup[j]) continue;
                    unsigned long long kj = keys[j];
                    int nj = (int)(0xFFFFFFFFu - (unsigned)(kj & 0xFFFFFFFFu));
                    const float* bj_p = boxes + (size_t)(b * NN + nj) * 4;
                    float tj = bj_p[0], lj = bj_p[1], bj = bj_p[2], rj = bj_p[3];
                    float aj = __fmul_rn(fmaxf(__fsub_rn(bj, tj), 0.0f),
                                         fmaxf(__fsub_rn(rj, lj), 0.0f));
                    float ih = fmaxf(__fsub_rn(fminf(bi, bj), fmaxf(ti, tj)), 0.0f);
                    float iw = fmaxf(__fsub_rn(fminf(ri, rj), fmaxf(li, lj)), 0.0f);
                    float inter = __fmul_rn(ih, iw);
                    float uni   = __fsub_rn(__fadd_rn(ai, aj), inter);
                    float iou   = __fdiv_rn(inter, fmaxf(uni, 1e-9f));
                    if (iou > 0.5f) sup[j] = 1;
                }
            }
            __syncthreads();
        }
    }
}

extern "C" void kernel_launch(void* const* d_in, const int* in_sizes, int n_in,
                              void* d_out, int out_size)
{
    const float* nms_reg  = (const float*)d_in[0];
    const float* nms_cls  = (const float*)d_in[1];
    const float* rcnn_reg = (const float*)d_in[2];
    const float* rcnn_cls = (const float*)d_in[3];
    const unsigned int* red = (const unsigned int*)d_in[4];
    float* out = (float*)d_out;

    prep_kernel<<<(BN + 255) / 256, 256>>>(nms_reg, nms_cls, rcnn_reg, rcnn_cls, red, out);
    nms_kernel<<<BB * (CC - 1), NMS_THREADS>>>(out);
}

// round 5
// speedup vs baseline: 2.2244x; 1.6600x over previous
#include <cuda_runtime.h>
#include <math.h>

#define BB 4
#define NN 3000
#define CC 21
#define BN (BB*NN)

// scratch (no allocations allowed)
__device__ signed char g_amax[BN];
__device__ float       g_score[BN];

// ---------------------------------------------------------------------------
// Kernel A: elementwise prep.
// out layout (float32): [rounded 4][sigmoid 1][boxes 4][probs C][keep 1] per-box blocks
// ---------------------------------------------------------------------------
__global__ void prep_kernel(const float* __restrict__ nms_reg,
                            const float* __restrict__ nms_cls,
                            const float* __restrict__ rcnn_reg,
                            const float* __restrict__ rcnn_cls,
                            const unsigned int* __restrict__ red_raw,
                            float* __restrict__ out)
{
    int idx = blockIdx.x * blockDim.x + threadIdx.x;
    if (idx >= BN) return;

    unsigned int w = red_raw[0];
    float red = (w < 0x10000u) ? (float)w : __uint_as_float(w);

    float* o_round = out;
    float* o_sig   = out + BN * 4;
    float* o_boxes = out + BN * 5;
    float* o_probs = out + BN * 9;
    float* o_keep  = out + BN * 9 + BN * CC;

    float r0 = nms_reg[idx * 4 + 0];
    float r1 = nms_reg[idx * 4 + 1];
    float r2 = nms_reg[idx * 4 + 2];
    float r3 = nms_reg[idx * 4 + 3];
    float q0 = floorf(__fmul_rn(r0, red)) / red;
    float q1 = floorf(__fmul_rn(r1, red)) / red;
    float q2 = ceilf(__fmul_rn(r2, red)) / red;
    float q3 = ceilf(__fmul_rn(r3, red)) / red;
    o_round[idx * 4 + 0] = q0;
    o_round[idx * 4 + 1] = q1;
    o_round[idx * 4 + 2] = q2;
    o_round[idx * 4 + 3] = q3;

    o_boxes[idx * 4 + 0] = __fadd_rn(rcnn_reg[idx * 4 + 0], q0);
    o_boxes[idx * 4 + 1] = __fadd_rn(rcnn_reg[idx * 4 + 1], q1);
    o_boxes[idx * 4 + 2] = __fadd_rn(rcnn_reg[idx * 4 + 2], q2);
    o_boxes[idx * 4 + 3] = __fadd_rn(rcnn_reg[idx * 4 + 3], q3);

    float s = nms_cls[idx];
    o_sig[idx] = 1.0f / (1.0f + expf(-s));

    float logit[CC];
    float m = -INFINITY;
    #pragma unroll
    for (int c = 0; c < CC; c++) {
        logit[c] = rcnn_cls[idx * CC + c];
        m = fmaxf(m, logit[c]);
    }
    float sum = 0.0f;
    float p[CC];
    #pragma unroll
    for (int c = 0; c < CC; c++) {
        p[c] = expf(logit[c] - m);
        sum += p[c];
    }
    float inv = 1.0f / sum;
    int   am   = 0;
    float best = -INFINITY;
    #pragma unroll
    for (int c = 0; c < CC; c++) {
        p[c] = __fmul_rn(p[c], inv);
        o_probs[idx * CC + c] = p[c];
        if (p[c] > best) { best = p[c]; am = c; }
    }
    g_amax[idx]  = (signed char)am;
    g_score[idx] = best;

    o_keep[idx] = 0.0f;
}

// ---------------------------------------------------------------------------
// Kernel B: per-(batch,class) greedy NMS. One block per group.
// Reference quirk: in-batch box index 0 is never kept (exhausted scan
// iterations clobber keep[0]); it still suppresses others.
// ---------------------------------------------------------------------------
#define NMS_THREADS 256
#define MAXM  320
#define WMAX  10

// sbuf overlay:
//   fast path:  keys u64 [0,4096) | tlbr f4 [4096,9216) | area f [9216,10496)
//               sidx i32 [10496,11776)
//   fallback:   keys u64 [0,32768)
__shared__ unsigned char sbuf[32768];
__shared__ unsigned int  maskbuf[MAXM * WMAX];
__shared__ int s_count;

__global__ void __launch_bounds__(NMS_THREADS)
nms_kernel(float* __restrict__ out)
{
    const float* boxes = out + BN * 5;
    float*       keep  = out + BN * 9 + BN * CC;

    int b   = blockIdx.x / (CC - 1);
    int cls = 1 + blockIdx.x % (CC - 1);
    int tid = threadIdx.x;
    int lane = tid & 31;

    unsigned long long* keys = (unsigned long long*)sbuf;

    if (tid == 0) s_count = 0;
    __syncthreads();

    // gather candidates of this class
    for (int n = tid; n < NN; n += NMS_THREADS) {
        if ((int)g_amax[b * NN + n] == cls) {
            int pos = atomicAdd(&s_count, 1);
            unsigned int sb = __float_as_uint(g_score[b * NN + n]);
            keys[pos] = ((unsigned long long)sb << 32)
                      | (unsigned long long)(0xFFFFFFFFu - (unsigned)n);
        }
    }
    __syncthreads();
    int M = s_count;
    if (M == 0) return;

    if (M <= MAXM) {
        // ---------------- fast path ----------------
        float4* tlbr = (float4*)(sbuf + 4096);
        float*  area = (float*)(sbuf + 9216);
        int*    sidx = (int*)(sbuf + 10496);
        const int W = (M + 31) >> 5;

        // rank sort (keys unique): rank = count of strictly-greater keys.
        unsigned long long myk[2]; int myrank[2]; int nown = 0;
        for (int i = tid; i < M; i += NMS_THREADS) {
            unsigned long long k = keys[i];
            int r = 0;
            for (int j = 0; j < M; j++) r += (keys[j] > k);
            myk[nown] = k; myrank[nown] = r; nown++;
        }
        __syncthreads();
        for (int q = 0; q < nown; q++) keys[myrank[q]] = myk[q];
        __syncthreads();

        // stage sorted boxes + areas + indices; zero bit matrix
        for (int i = tid; i < M; i += NMS_THREADS) {
            int n = (int)(0xFFFFFFFFu - (unsigned)(keys[i] & 0xFFFFFFFFu));
            sidx[i] = n;
            const float* bp = boxes + (size_t)(b * NN + n) * 4;
            float4 v = make_float4(bp[0], bp[1], bp[2], bp[3]);
            tlbr[i] = v;
            area[i] = __fmul_rn(fmaxf(__fsub_rn(v.z, v.x), 0.0f),
                                fmaxf(__fsub_rn(v.w, v.y), 0.0f));
        }
        for (int t = tid; t < M * W; t += NMS_THREADS) maskbuf[t] = 0;
        __syncthreads();

        // suppression matrix over upper triangle (j > i), pair-indexed.
        int npairs = (M * (M - 1)) >> 1;
        for (int t = tid; t < npairs; t += NMS_THREADS) {
            // map t -> (i, j) with pairs ordered by j: t = j*(j-1)/2 + i
            int j = (int)((1.0f + sqrtf(1.0f + 8.0f * (float)t)) * 0.5f);
            while ((j * (j - 1)) >> 1 > t) j--;
            while (((j + 1) * j) >> 1 <= t) j++;
            int i = t - ((j * (j - 1)) >> 1);
            float4 bi = tlbr[i];
            float4 bj = tlbr[j];
            float ih = fmaxf(__fsub_rn(fminf(bi.z, bj.z), fmaxf(bi.x, bj.x)), 0.0f);
            float iw = fmaxf(__fsub_rn(fminf(bi.w, bj.w), fmaxf(bi.y, bj.y)), 0.0f);
            float inter = __fmul_rn(ih, iw);
            float uni   = __fsub_rn(__fadd_rn(area[i], area[j]), inter);
            float iou   = __fdiv_rn(inter, fmaxf(uni, 1e-9f));
            if (iou > 0.5f)
                atomicOr(&maskbuf[i * W + (j >> 5)], 1u << (j & 31));
        }
        __syncthreads();

        // warp 0: branchless chunked greedy scan.
        if (tid < 32) {
            unsigned int R = 0u;   // lane w owns removed-word w
            unsigned int K = 0u;   // lane w owns kept-word w
            int ldslane = (lane < W) ? lane : (W - 1);
            unsigned int lanemask = (lane < W) ? 0xFFFFFFFFu : 0u;
            int nchunks = W;
            for (int c = 0; c < nchunks; c++) {
                unsigned int curw = __shfl_sync(0xFFFFFFFFu, R, c);
                int ibase = c << 5;
                #pragma unroll 8
                for (int bit = 0; bit < 32; bit++) {
                    int i = ibase + bit;
                    unsigned int valid = (i < M) ? 0xFFFFFFFFu : 0u;
                    unsigned int keptm = (~(curw >> bit) & 1u) ? valid : 0u;
                    // row words (address independent of scan state -> pipelined)
                    unsigned int mwc = maskbuf[i * W + c]        & valid;
                    unsigned int mwl = maskbuf[i * W + ldslane]  & lanemask & valid;
                    curw |= (mwc & keptm);
                    R    |= (mwl & keptm);
                    K    |= ((lane == c) ? (keptm & (1u << bit)) : 0u);
                }
            }
            // write keep bits (outside the serial chain)
            if (lane < W) {
                unsigned int kk = K;
                while (kk) {
                    int bit = __ffs(kk) - 1;
                    kk &= kk - 1;
                    int n = sidx[(lane << 5) + bit];
                    if (n != 0) keep[b * NN + n] = 1.0f;
                }
            }
        }
    } else {
        // ---------------- fallback (never expected for this dataset) --------
        // pad to next power of two >= M, bitonic sort
        int P = 1;
        while (P < M) P <<= 1;
        for (int i = M + tid; i < P; i += NMS_THREADS) keys[i] = 0ULL;
        __syncthreads();
        for (int k = 2; k <= P; k <<= 1) {
            for (int j = k >> 1; j > 0; j >>= 1) {
                for (int i = tid; i < P; i += NMS_THREADS) {
                    int ixj = i ^ j;
                    if (ixj > i) {
                        unsigned long long a = keys[i];
                        unsigned long long c = keys[ixj];
                        bool dirDesc = ((i & k) == 0);
                        if ((a < c) == dirDesc) { keys[i] = c; keys[ixj] = a; }
                    }
                }
                __syncthreads();
            }
        }
        unsigned char* sup = (unsigned char*)maskbuf;
        for (int i = tid; i < M; i += NMS_THREADS) sup[i] = 0;
        __syncthreads();
        for (int i = 0; i < M; i++) {
            if (!sup[i]) {
                unsigned long long ki = keys[i];
                int ni = (int)(0xFFFFFFFFu - (unsigned)(ki & 0xFFFFFFFFu));
                const float* bi_p = boxes + (size_t)(b * NN + ni) * 4;
                float ti = bi_p[0], li = bi_p[1], bi = bi_p[2], ri = bi_p[3];
                float ai = __fmul_rn(fmaxf(__fsub_rn(bi, ti), 0.0f),
                                     fmaxf(__fsub_rn(ri, li), 0.0f));
                if (tid == 0 && ni != 0) keep[b * NN + ni] = 1.0f;
                for (int j = i + 1 + tid; j < M; j += NMS_THREADS) {
                    if (sup[j]) continue;
                    unsigned long long kj = keys[j];
                    int nj = (int)(0xFFFFFFFFu - (unsigned)(kj & 0xFFFFFFFFu));
                    const float* bj_p = boxes + (size_t)(b * NN + nj) * 4;
                    float tj = bj_p[0], lj = bj_p[1], bj = bj_p[2], rj = bj_p[3];
                    float aj = __fmul_rn(fmaxf(__fsub_rn(bj, tj), 0.0f),
                                         fmaxf(__fsub_rn(rj, lj), 0.0f));
                    float ih = fmaxf(__fsub_rn(fminf(bi, bj), fmaxf(ti, tj)), 0.0f);
                    float iw = fmaxf(__fsub_rn(fminf(ri, rj), fmaxf(li, lj)), 0.0f);
                    float inter = __fmul_rn(ih, iw);
                    float uni   = __fsub_rn(__fadd_rn(ai, aj), inter);
                    float iou   = __fdiv_rn(inter, fmaxf(uni, 1e-9f));
                    if (iou > 0.5f) sup[j] = 1;
                }
            }
            __syncthreads();
        }
    }
}

extern "C" void kernel_launch(void* const* d_in, const int* in_sizes, int n_in,
                              void* d_out, int out_size)
{
    const float* nms_reg  = (const float*)d_in[0];
    const float* nms_cls  = (const float*)d_in[1];
    const float* rcnn_reg = (const float*)d_in[2];
    const float* rcnn_cls = (const float*)d_in[3];
    const unsigned int* red = (const unsigned int*)d_in[4];
    float* out = (float*)d_out;

    prep_kernel<<<(BN + 255) / 256, 256>>>(nms_reg, nms_cls, rcnn_reg, rcnn_cls, red, out);
    nms_kernel<<<BB * (CC - 1), NMS_THREADS>>>(out);
}

// round 6
// speedup vs baseline: 2.6196x; 1.1776x over previous
#include <cuda_runtime.h>
#include <math.h>

#define BB 4
#define NN 3000
#define CC 21
#define BN (BB*NN)

#define NGROUPS (BB*(CC-1))       // 80
#define THREADS 512
#define PREP_BLOCKS ((BN + THREADS - 1) / THREADS)   // 24
#define MAXM  320
#define WMAX  10

// ---------------------------------------------------------------------------
// out layout (float32): [rounded BN*4][sigmoid BN][boxes BN*4][probs BN*C][keep BN]
// ---------------------------------------------------------------------------

// sbuf overlay (group path):
//   keys u64 [0,4096) | tlbr f4 [4096,9216) | area f [9216,10496) | sidx i32 [10496,11776)
//   keptw u32 [11776, 11776+40)
//   fallback: keys u64 [0,32768), state bytes in maskbuf
__shared__ unsigned char sbuf[32768];
__shared__ unsigned int  maskbuf[MAXM * WMAX];
__shared__ int s_count;

// exact reference-sequence softmax score for class `cls` given 21 logits.
// m must equal the fmaxf-chain max (== max value).
__device__ __forceinline__ float softmax_score(const float* l, float m, int cls)
{
    float sum = 0.0f;
    #pragma unroll
    for (int c = 0; c < CC; c++) sum += expf(l[c] - m);
    float inv = __fdiv_rn(1.0f, sum);
    return __fmul_rn(expf(l[cls] - m), inv);
}

__device__ __forceinline__ void load_box(const float* __restrict__ nms_reg,
                                         const float* __restrict__ rcnn_reg,
                                         float red, int gidx, float4* box)
{
    float r0 = nms_reg[gidx * 4 + 0];
    float r1 = nms_reg[gidx * 4 + 1];
    float r2 = nms_reg[gidx * 4 + 2];
    float r3 = nms_reg[gidx * 4 + 3];
    float q0 = __fdiv_rn(floorf(__fmul_rn(r0, red)), red);
    float q1 = __fdiv_rn(floorf(__fmul_rn(r1, red)), red);
    float q2 = __fdiv_rn(ceilf(__fmul_rn(r2, red)), red);
    float q3 = __fdiv_rn(ceilf(__fmul_rn(r3, red)), red);
    box->x = __fadd_rn(rcnn_reg[gidx * 4 + 0], q0);
    box->y = __fadd_rn(rcnn_reg[gidx * 4 + 1], q1);
    box->z = __fadd_rn(rcnn_reg[gidx * 4 + 2], q2);
    box->w = __fadd_rn(rcnn_reg[gidx * 4 + 3], q3);
}

__global__ void __launch_bounds__(THREADS)
fused_kernel(const float* __restrict__ nms_reg,
             const float* __restrict__ nms_cls,
             const float* __restrict__ rcnn_reg,
             const float* __restrict__ rcnn_cls,
             const unsigned int* __restrict__ red_raw,
             float* __restrict__ out)
{
    int tid  = threadIdx.x;
    int lane = tid & 31;

    unsigned int wr = red_raw[0];
    float red = (wr < 0x10000u) ? (float)wr : __uint_as_float(wr);

    float* o_keep = out + BN * 9 + BN * CC;

    if (blockIdx.x >= NGROUPS) {
        // ------------------------- prep path -------------------------
        int idx = (blockIdx.x - NGROUPS) * THREADS + tid;
        if (idx >= BN) return;

        float* o_round = out;
        float* o_sig   = out + BN * 4;
        float* o_boxes = out + BN * 5;
        float* o_probs = out + BN * 9;

        float r0 = nms_reg[idx * 4 + 0];
        float r1 = nms_reg[idx * 4 + 1];
        float r2 = nms_reg[idx * 4 + 2];
        float r3 = nms_reg[idx * 4 + 3];
        float q0 = __fdiv_rn(floorf(__fmul_rn(r0, red)), red);
        float q1 = __fdiv_rn(floorf(__fmul_rn(r1, red)), red);
        float q2 = __fdiv_rn(ceilf(__fmul_rn(r2, red)), red);
        float q3 = __fdiv_rn(ceilf(__fmul_rn(r3, red)), red);
        o_round[idx * 4 + 0] = q0;
        o_round[idx * 4 + 1] = q1;
        o_round[idx * 4 + 2] = q2;
        o_round[idx * 4 + 3] = q3;

        o_boxes[idx * 4 + 0] = __fadd_rn(rcnn_reg[idx * 4 + 0], q0);
        o_boxes[idx * 4 + 1] = __fadd_rn(rcnn_reg[idx * 4 + 1], q1);
        o_boxes[idx * 4 + 2] = __fadd_rn(rcnn_reg[idx * 4 + 2], q2);
        o_boxes[idx * 4 + 3] = __fadd_rn(rcnn_reg[idx * 4 + 3], q3);

        float s = nms_cls[idx];
        o_sig[idx] = 1.0f / (1.0f + expf(-s));

        float logit[CC];
        float m = -INFINITY;
        #pragma unroll
        for (int c = 0; c < CC; c++) {
            logit[c] = rcnn_cls[idx * CC + c];
            m = fmaxf(m, logit[c]);
        }
        float sum = 0.0f;
        float p[CC];
        #pragma unroll
        for (int c = 0; c < CC; c++) {
            p[c] = expf(logit[c] - m);
            sum += p[c];
        }
        float inv = __fdiv_rn(1.0f, sum);
        int   am   = 0;
        float best = -INFINITY;
        #pragma unroll
        for (int c = 0; c < CC; c++) {
            p[c] = __fmul_rn(p[c], inv);
            o_probs[idx * CC + c] = p[c];
            if (p[c] > best) { best = p[c]; am = c; }
        }
        // keep: prep owns only amax==0 boxes (never kept); group blocks own the rest.
        if (am == 0) o_keep[idx] = 0.0f;
        return;
    }

    // ------------------------- group path -------------------------
    int b   = blockIdx.x / (CC - 1);
    int cls = 1 + blockIdx.x % (CC - 1);

    unsigned long long* keys = (unsigned long long*)sbuf;

    if (tid == 0) s_count = 0;
    __syncthreads();

    // gather: determine candidates of this class from raw logits.
    for (int n = tid; n < NN; n += THREADS) {
        const float* lg = rcnn_cls + (size_t)(b * NN + n) * CC;
        float l[CC];
        float best = -INFINITY, second = -INFINITY;
        int am = 0;
        #pragma unroll
        for (int c = 0; c < CC; c++) {
            float v = lg[c];
            l[c] = v;
            if (v > best) { second = best; best = v; am = c; }
            else if (v > second) second = v;
        }
        bool cand;
        float score = 0.0f;
        if (best - second > 1e-5f) {
            // unique max: argmax(probs) == argmax(logits)
            cand = (am == cls);
            if (cand) score = softmax_score(l, best, cls);
        } else {
            // near-tie: replicate exact reference p computation + first-max argmax
            float sum = 0.0f;
            float p[CC];
            #pragma unroll
            for (int c = 0; c < CC; c++) { p[c] = expf(l[c] - best); sum += p[c]; }
            float inv = __fdiv_rn(1.0f, sum);
            int amp = 0; float bp = -INFINITY;
            #pragma unroll
            for (int c = 0; c < CC; c++) {
                p[c] = __fmul_rn(p[c], inv);
                if (p[c] > bp) { bp = p[c]; amp = c; }
            }
            cand = (amp == cls);
            score = p[cls];
        }
        if (cand) {
            int pos = atomicAdd(&s_count, 1);
            unsigned int sb = __float_as_uint(score);
            keys[pos] = ((unsigned long long)sb << 32)
                      | (unsigned long long)(0xFFFFFFFFu - (unsigned)n);
        }
    }
    __syncthreads();
    int M = s_count;
    if (M == 0) return;

    if (M <= MAXM) {
        float4* tlbr = (float4*)(sbuf + 4096);
        float*  area = (float*)(sbuf + 9216);
        int*    sidx = (int*)(sbuf + 10496);
        unsigned int* keptw = (unsigned int*)(sbuf + 11776);
        const int W = (M + 31) >> 5;

        // rank sort (keys unique)
        unsigned long long myk; int myrank = -1;
        if (tid < M) {
            myk = keys[tid];
            int r = 0;
            for (int j = 0; j < M; j++) r += (keys[j] > myk);
            myrank = r;
        }
        __syncthreads();
        if (myrank >= 0) keys[myrank] = myk;
        __syncthreads();

        // stage sorted boxes (recomputed from inputs, bit-exact) + areas + indices
        if (tid < M) {
            int n = (int)(0xFFFFFFFFu - (unsigned)(keys[tid] & 0xFFFFFFFFu));
            sidx[tid] = n;
            float4 v;
            load_box(nms_reg, rcnn_reg, red, b * NN + n, &v);
            tlbr[tid] = v;
            area[tid] = __fmul_rn(fmaxf(__fsub_rn(v.z, v.x), 0.0f),
                                  fmaxf(__fsub_rn(v.w, v.y), 0.0f));
        }
        for (int t = tid; t < M * W; t += THREADS) maskbuf[t] = 0;
        __syncthreads();

        // suppression matrix, upper triangle (j > i)
        int npairs = (M * (M - 1)) >> 1;
        for (int t = tid; t < npairs; t += THREADS) {
            int j = (int)((1.0f + sqrtf(1.0f + 8.0f * (float)t)) * 0.5f);
            while ((j * (j - 1)) >> 1 > t) j--;
            while (((j + 1) * j) >> 1 <= t) j++;
            int i = t - ((j * (j - 1)) >> 1);
            float4 bi = tlbr[i];
            float4 bj = tlbr[j];
            float ih = fmaxf(__fsub_rn(fminf(bi.z, bj.z), fmaxf(bi.x, bj.x)), 0.0f);
            float iw = fmaxf(__fsub_rn(fminf(bi.w, bj.w), fmaxf(bi.y, bj.y)), 0.0f);
            float inter = __fmul_rn(ih, iw);
            float uni   = __fsub_rn(__fadd_rn(area[i], area[j]), inter);
            float iou   = __fdiv_rn(inter, fmaxf(uni, 1e-9f));
            if (iou > 0.5f)
                atomicOr(&maskbuf[i * W + (j >> 5)], 1u << (j & 31));
        }
        __syncthreads();

        // warp 0: branchless chunked greedy scan
        if (tid < 32) {
            unsigned int R = 0u, K = 0u;
            int ldslane = (lane < W) ? lane : (W - 1);
            unsigned int lanemask = (lane < W) ? 0xFFFFFFFFu : 0u;
            for (int c = 0; c < W; c++) {
                unsigned int curw = __shfl_sync(0xFFFFFFFFu, R, c);
                int ibase = c << 5;
                #pragma unroll 8
                for (int bit = 0; bit < 32; bit++) {
                    int i = ibase + bit;
                    unsigned int valid = (i < M) ? 0xFFFFFFFFu : 0u;
                    unsigned int keptm = (~(curw >> bit) & 1u) ? valid : 0u;
                    unsigned int mwc = maskbuf[i * W + c]       & valid;
                    unsigned int mwl = maskbuf[i * W + ldslane] & lanemask & valid;
                    curw |= (mwc & keptm);
                    R    |= (mwl & keptm);
                    K    |= ((lane == c) ? (keptm & (1u << bit)) : 0u);
                }
            }
            if (lane < W) keptw[lane] = K;
        }
        __syncthreads();

        // write keep (0/1) for ALL owned candidates; in-batch index 0 never kept.
        if (tid < M) {
            int n = sidx[tid];
            bool kept = (keptw[tid >> 5] >> (tid & 31)) & 1u;
            o_keep[b * NN + n] = (kept && n != 0) ? 1.0f : 0.0f;
        }
    } else {
        // -------- fallback (statistically unreachable; M>320) --------
        int P = 1;
        while (P < M) P <<= 1;
        for (int i = M + tid; i < P; i += THREADS) keys[i] = 0ULL;
        __syncthreads();
        for (int k = 2; k <= P; k <<= 1) {
            for (int j = k >> 1; j > 0; j >>= 1) {
                for (int i = tid; i < P; i += THREADS) {
                    int ixj = i ^ j;
                    if (ixj > i) {
                        unsigned long long a = keys[i];
                        unsigned long long c = keys[ixj];
                        bool dirDesc = ((i & k) == 0);
                        if ((a < c) == dirDesc) { keys[i] = c; keys[ixj] = a; }
                    }
                }
                __syncthreads();
            }
        }
        unsigned char* st = (unsigned char*)maskbuf;   // 0=alive, 1=suppressed, 2=kept
        for (int i = tid; i < M; i += THREADS) st[i] = 0;
        __syncthreads();
        for (int i = 0; i < M; i++) {
            if (st[i] == 0) {
                int ni = (int)(0xFFFFFFFFu - (unsigned)(keys[i] & 0xFFFFFFFFu));
                float4 vi; load_box(nms_reg, rcnn_reg, red, b * NN + ni, &vi);
                float ai = __fmul_rn(fmaxf(__fsub_rn(vi.z, vi.x), 0.0f),
                                     fmaxf(__fsub_rn(vi.w, vi.y), 0.0f));
                if (tid == 0) st[i] = 2;
                for (int j = i + 1 + tid; j < M; j += THREADS) {
                    if (st[j]) continue;
                    int nj = (int)(0xFFFFFFFFu - (unsigned)(keys[j] & 0xFFFFFFFFu));
                    float4 vj; load_box(nms_reg, rcnn_reg, red, b * NN + nj, &vj);
                    float aj = __fmul_rn(fmaxf(__fsub_rn(vj.z, vj.x), 0.0f),
                                         fmaxf(__fsub_rn(vj.w, vj.y), 0.0f));
                    float ih = fmaxf(__fsub_rn(fminf(vi.z, vj.z), fmaxf(vi.x, vj.x)), 0.0f);
                    float iw = fmaxf(__fsub_rn(fminf(vi.w, vj.w), fmaxf(vi.y, vj.y)), 0.0f);
                    float inter = __fmul_rn(ih, iw);
                    float uni   = __fsub_rn(__fadd_rn(ai, aj), inter);
                    float iou   = __fdiv_rn(inter, fmaxf(uni, 1e-9f));
                    if (iou > 0.5f) st[j] = 1;
                }
            }
            __syncthreads();
        }
        for (int i = tid; i < M; i += THREADS) {
            int n = (int)(0xFFFFFFFFu - (unsigned)(keys[i] & 0xFFFFFFFFu));
            o_keep[b * NN + n] = (st[i] == 2 && n != 0) ? 1.0f : 0.0f;
        }
    }
}

extern "C" void kernel_launch(void* const* d_in, const int* in_sizes, int n_in,
                              void* d_out, int out_size)
{
    const float* nms_reg  = (const float*)d_in[0];
    const float* nms_cls  = (const float*)d_in[1];
    const float* rcnn_reg = (const float*)d_in[2];
    const float* rcnn_cls = (const float*)d_in[3];
    const unsigned int* red = (const unsigned int*)d_in[4];
    float* out = (float*)d_out;

    fused_kernel<<<NGROUPS + PREP_BLOCKS, THREADS>>>(
        nms_reg, nms_cls, rcnn_reg, rcnn_cls, red, out);
}